// round 9
// baseline (speedup 1.0000x reference)
#include <cuda_runtime.h>
#include <cuda_bf16.h>
#include <cuda_fp16.h>
#include <cstdint>

// Problem constants (fixed by the dataset)
#define NN      50000
#define FDIM    128
#define HEADS   4
#define NGRAPH  64
#define OUTCH   10
#define NEG     0.2f
#define MAXE    800000
#define MAXTOT  (MAXE + NN)   // edges + self loops

// ---------------- device scratch (static, no allocation) ----------------
__device__ __align__(16) __half g_Hh[NN * FDIM];   // gemm output (pre-bias h), fp16
__device__ __align__(16) float  g_P[NN * FDIM];    // ping buffer
__device__ __align__(16) float  g_Q[NN * FDIM];    // pong buffer
__device__ __align__(16) float  g_asrc[NN * HEADS];
__device__ __align__(16) float  g_adst[NN * HEADS];
__device__ __align__(16) float  g_ex[MAXTOT * HEADS]; // exp(e) per edge per head
__device__ __align__(16) float  g_pooled[NGRAPH * FDIM];
// CSR by destination (built once per launch; graph static across layers)
__device__ int g_deg[NN];
__device__ int g_off[NN + 1];
__device__ int g_cursor[NN];
__device__ int g_csr_src[MAXTOT];

__device__ __forceinline__ float lrelu(float e) { return e > 0.f ? e : NEG * e; }

__device__ __forceinline__ float* sel_buf(int sel) {
    return sel == 1 ? g_P : g_Q;
}
__device__ __forceinline__ const float* sel_x(const float* ext, int sel) {
    return sel == 0 ? ext : (sel == 1 ? g_P : g_Q);
}

// ================= CSR build (once per launch) =================
__global__ void init_deg() {
    int i = blockIdx.x * blockDim.x + threadIdx.x;
    if (i < NN) g_deg[i] = 1;          // self loop
}
__global__ void count_deg(const int* __restrict__ dsts, int E) {
    int i = blockIdx.x * blockDim.x + threadIdx.x;
    if (i < E) atomicAdd(&g_deg[dsts[i]], 1);
}
// one block, 1024 threads: chunked exclusive scan of g_deg -> g_off, g_cursor
__global__ void scan_deg() {
    __shared__ int part[1024];
    const int CH = (NN + 1023) / 1024;   // 49
    int t = threadIdx.x;
    int base = t * CH;
    int s = 0;
    for (int k = 0; k < CH; k++) {
        int idx = base + k;
        if (idx < NN) s += g_deg[idx];
    }
    part[t] = s;
    __syncthreads();
    for (int off = 1; off < 1024; off <<= 1) {
        int v = (t >= off) ? part[t - off] : 0;
        __syncthreads();
        part[t] += v;
        __syncthreads();
    }
    int run = part[t] - s;     // exclusive start of this chunk
    for (int k = 0; k < CH; k++) {
        int idx = base + k;
        if (idx < NN) {
            g_off[idx]    = run;
            g_cursor[idx] = run;
            run += g_deg[idx];
        }
    }
    if (t == 0) g_off[NN] = part[1023];
}
__global__ void scatter_edges(const int* __restrict__ srcs,
                              const int* __restrict__ dsts, int E, int total) {
    int i = blockIdx.x * blockDim.x + threadIdx.x;
    if (i >= total) return;
    int s, d;
    if (i < E) { s = srcs[i]; d = dsts[i]; }
    else       { s = d = i - E; }
    int pos = atomicAdd(&g_cursor[d], 1);
    g_csr_src[pos] = s;
}

// ======= GEMM via mma.sync fp16 hi/lo split: H = X(N,128) @ W(128,128) =======
// 128-row tile per block, 256 threads (8 warps x 16 rows). Fused attn epilogue.
// W converted fp32 -> fp16 hi/lo in-kernel (no separate conv kernel).
#define SA 136                    // smem row stride in halfs (conflict-free)
#define GSM_BYTES (4 * 128 * SA * 2)   // Ahi, Alo, Bhi, Blo = 139264 B

__device__ __forceinline__ void mma16816(float* c, uint32_t a0, uint32_t a1,
                                         uint32_t a2, uint32_t a3,
                                         uint32_t b0, uint32_t b1) {
    asm volatile(
        "mma.sync.aligned.m16n8k16.row.col.f32.f16.f16.f32 "
        "{%0,%1,%2,%3}, {%4,%5,%6,%7}, {%8,%9}, {%0,%1,%2,%3};"
        : "+f"(c[0]), "+f"(c[1]), "+f"(c[2]), "+f"(c[3])
        : "r"(a0), "r"(a1), "r"(a2), "r"(a3), "r"(b0), "r"(b1));
}

__global__ void __launch_bounds__(256) gemm_mma(const float* __restrict__ Xext,
                                                int xsel,
                                                const float* __restrict__ W,
                                                const float* __restrict__ a_s,
                                                const float* __restrict__ a_d) {
    extern __shared__ __align__(16) __half smh[];
    __half* Ahi = smh;
    __half* Alo = Ahi + 128 * SA;
    __half* Bhi = Alo + 128 * SA;
    __half* Blo = Bhi + 128 * SA;
    __shared__ float as_s[128], ad_s[128];

    const float* X = sel_x(Xext, xsel);
    const int tid  = threadIdx.x;
    const int lane = tid & 31;
    const int wid  = tid >> 5;
    const int g    = lane >> 2;       // 0..7
    const int c    = lane & 3;        // 0..3
    const int row0 = blockIdx.x * 128;
    const int arow = wid * 16 + g;    // fragment row within tile

    if (tid < 128) { as_s[tid] = a_s[tid]; ad_s[tid] = a_d[tid]; }

    // ---- fill A tiles (X fp32 -> fp16 hi/lo) ----
    for (int it = tid; it < 128 * 32; it += 256) {
        int r = it >> 5, j = it & 31;          // j: float4 col
        float4 v = make_float4(0.f, 0.f, 0.f, 0.f);
        if (row0 + r < NN)
            v = reinterpret_cast<const float4*>(X)[(row0 + r) * 32 + j];
        __half hx = __float2half_rn(v.x), hy = __float2half_rn(v.y);
        __half hz = __float2half_rn(v.z), hw = __float2half_rn(v.w);
        __half lx = __float2half_rn(v.x - __half2float(hx));
        __half ly = __float2half_rn(v.y - __half2float(hy));
        __half lz = __float2half_rn(v.z - __half2float(hz));
        __half lw = __float2half_rn(v.w - __half2float(hw));
        __half2 h01 = __halves2half2(hx, hy), h23 = __halves2half2(hz, hw);
        __half2 l01 = __halves2half2(lx, ly), l23 = __halves2half2(lz, lw);
        uint2 hv = make_uint2(*(uint32_t*)&h01, *(uint32_t*)&h23);
        uint2 lv = make_uint2(*(uint32_t*)&l01, *(uint32_t*)&l23);
        *reinterpret_cast<uint2*>(&Ahi[r * SA + 4 * j]) = hv;
        *reinterpret_cast<uint2*>(&Alo[r * SA + 4 * j]) = lv;
    }
    // ---- fill B tiles: W[k][n] fp32 -> Bhi/Blo[n][k] fp16 (transposed) ----
    for (int it = tid; it < 128 * 32; it += 256) {
        int k = it >> 5, j = it & 31;          // j: float4 col over n
        float4 w4 = reinterpret_cast<const float4*>(W)[k * 32 + j];
        float v[4] = {w4.x, w4.y, w4.z, w4.w};
#pragma unroll
        for (int q = 0; q < 4; q++) {
            int n = 4 * j + q;
            __half h = __float2half_rn(v[q]);
            __half l = __float2half_rn(v[q] - __half2float(h));
            Bhi[n * SA + k] = h;
            Blo[n * SA + k] = l;
        }
    }
    __syncthreads();

    // ---- mainloop ----
    float acc[16][4];
#pragma unroll
    for (int nt = 0; nt < 16; nt++)
#pragma unroll
        for (int q = 0; q < 4; q++) acc[nt][q] = 0.f;

#pragma unroll
    for (int ks = 0; ks < 8; ks++) {
        const int kb = ks * 16 + 2 * c;
        uint32_t ah0 = *(uint32_t*)&Ahi[arow * SA + kb];
        uint32_t ah1 = *(uint32_t*)&Ahi[(arow + 8) * SA + kb];
        uint32_t ah2 = *(uint32_t*)&Ahi[arow * SA + kb + 8];
        uint32_t ah3 = *(uint32_t*)&Ahi[(arow + 8) * SA + kb + 8];
        uint32_t al0 = *(uint32_t*)&Alo[arow * SA + kb];
        uint32_t al1 = *(uint32_t*)&Alo[(arow + 8) * SA + kb];
        uint32_t al2 = *(uint32_t*)&Alo[arow * SA + kb + 8];
        uint32_t al3 = *(uint32_t*)&Alo[(arow + 8) * SA + kb + 8];
#pragma unroll
        for (int nt = 0; nt < 16; nt++) {
            const int nrow = nt * 8 + g;
            uint32_t bh0 = *(uint32_t*)&Bhi[nrow * SA + kb];
            uint32_t bh1 = *(uint32_t*)&Bhi[nrow * SA + kb + 8];
            uint32_t bl0 = *(uint32_t*)&Blo[nrow * SA + kb];
            uint32_t bl1 = *(uint32_t*)&Blo[nrow * SA + kb + 8];
            mma16816(acc[nt], ah0, ah1, ah2, ah3, bh0, bh1);
            mma16816(acc[nt], ah0, ah1, ah2, ah3, bl0, bl1);
            mma16816(acc[nt], al0, al1, al2, al3, bh0, bh1);
        }
    }

    // ---- epilogue: attn scalars from accumulators + fp16 H store ----
    float ps[2][4], pd[2][4];
#pragma unroll
    for (int r2 = 0; r2 < 2; r2++)
#pragma unroll
        for (int h = 0; h < 4; h++) { ps[r2][h] = 0.f; pd[r2][h] = 0.f; }

#pragma unroll
    for (int nt = 0; nt < 16; nt++) {
        const int head = nt >> 2;
        const int col = nt * 8 + 2 * c;
        float s0 = as_s[col], s1 = as_s[col + 1];
        float d0 = ad_s[col], d1 = ad_s[col + 1];
        ps[0][head] += acc[nt][0] * s0 + acc[nt][1] * s1;
        pd[0][head] += acc[nt][0] * d0 + acc[nt][1] * d1;
        ps[1][head] += acc[nt][2] * s0 + acc[nt][3] * s1;
        pd[1][head] += acc[nt][2] * d0 + acc[nt][3] * d1;
    }
#pragma unroll
    for (int off = 1; off <= 2; off <<= 1)
#pragma unroll
        for (int r2 = 0; r2 < 2; r2++)
#pragma unroll
            for (int h = 0; h < 4; h++) {
                ps[r2][h] += __shfl_xor_sync(0xffffffffu, ps[r2][h], off);
                pd[r2][h] += __shfl_xor_sync(0xffffffffu, pd[r2][h], off);
            }
    if (c == 0) {
        int rA = row0 + arow, rB = rA + 8;
        if (rA < NN) {
            reinterpret_cast<float4*>(g_asrc)[rA] =
                make_float4(ps[0][0], ps[0][1], ps[0][2], ps[0][3]);
            reinterpret_cast<float4*>(g_adst)[rA] =
                make_float4(pd[0][0], pd[0][1], pd[0][2], pd[0][3]);
        }
        if (rB < NN) {
            reinterpret_cast<float4*>(g_asrc)[rB] =
                make_float4(ps[1][0], ps[1][1], ps[1][2], ps[1][3]);
            reinterpret_cast<float4*>(g_adst)[rB] =
                make_float4(pd[1][0], pd[1][1], pd[1][2], pd[1][3]);
        }
    }

    {
        int rA = row0 + arow, rB = rA + 8;
#pragma unroll
        for (int nt = 0; nt < 16; nt++) {
            const int col = nt * 8 + 2 * c;
            if (rA < NN) {
                __half2 v = __floats2half2_rn(acc[nt][0], acc[nt][1]);
                *reinterpret_cast<uint32_t*>(&g_Hh[rA * 128 + col]) =
                    *reinterpret_cast<uint32_t*>(&v);
            }
            if (rB < NN) {
                __half2 v = __floats2half2_rn(acc[nt][2], acc[nt][3]);
                *reinterpret_cast<uint32_t*>(&g_Hh[rB * 128 + col]) =
                    *reinterpret_cast<uint32_t*>(&v);
            }
        }
    }
}

// ======= fused softmax + aggregate: one warp per destination node =======
// No max pass (softmax shift-invariant; exp clamped at 30). exp(e) cached in
// g_ex. Pass 2 has NO shfl / NO predication: every lane loads its head's
// alpha from the same 16B sector (broadcast) -> deep software pipelining.
__global__ void __launch_bounds__(256) fused_edge(int aggsel,
                                                  const float* __restrict__ b) {
    int gw   = (blockIdx.x * blockDim.x + threadIdx.x) >> 5;
    int lane = threadIdx.x & 31;
    if (gw >= NN) return;
    const int d   = gw;
    const int beg = g_off[d];
    const int end = g_off[d + 1];   // >= beg+1 (self loop)

    float4 ad4 = reinterpret_cast<const float4*>(g_adst)[d];

    // pass 1: exp(e) per edge (cached) + per-head denominator
    float s0 = 0.f, s1 = 0.f, s2 = 0.f, s3 = 0.f;
    for (int i = beg + lane; i < end; i += 32) {
        int s = g_csr_src[i];
        float4 as = reinterpret_cast<const float4*>(g_asrc)[s];
        float x0 = __expf(fminf(lrelu(as.x + ad4.x), 30.f));
        float x1 = __expf(fminf(lrelu(as.y + ad4.y), 30.f));
        float x2 = __expf(fminf(lrelu(as.z + ad4.z), 30.f));
        float x3 = __expf(fminf(lrelu(as.w + ad4.w), 30.f));
        reinterpret_cast<float4*>(g_ex)[i] = make_float4(x0, x1, x2, x3);
        s0 += x0; s1 += x1; s2 += x2; s3 += x3;
    }
#pragma unroll
    for (int off = 16; off > 0; off >>= 1) {
        s0 += __shfl_xor_sync(0xffffffffu, s0, off);
        s1 += __shfl_xor_sync(0xffffffffu, s1, off);
        s2 += __shfl_xor_sync(0xffffffffu, s2, off);
        s3 += __shfl_xor_sync(0xffffffffu, s3, off);
    }

    __threadfence_block();   // make this warp's g_ex stores visible to all lanes
    __syncwarp();

    // per-lane reciprocal denominator for this lane's head (lane>>3)
    const int h = lane >> 3;
    float sh = (h & 2) ? ((h & 1) ? s3 : s2) : ((h & 1) ? s1 : s0);
    float rh = 1.f / (sh + 1e-16f);

    // pass 2: whole-warp per edge; no shfl, no predication; unroll for MLP
    float4 acc = make_float4(0.f, 0.f, 0.f, 0.f);
    const int exh = h;   // byte offset into the edge's 16B alpha record
    int i = beg;
#pragma unroll 4
    for (; i + 3 < end; i += 4) {
        int sA = g_csr_src[i + 0];
        int sB = g_csr_src[i + 1];
        int sC = g_csr_src[i + 2];
        int sD = g_csr_src[i + 3];
        float aA = g_ex[(i + 0) * 4 + exh];
        float aB = g_ex[(i + 1) * 4 + exh];
        float aC = g_ex[(i + 2) * 4 + exh];
        float aD = g_ex[(i + 3) * 4 + exh];
        uint2 hA = reinterpret_cast<const uint2*>(g_Hh)[sA * 32 + lane];
        uint2 hB = reinterpret_cast<const uint2*>(g_Hh)[sB * 32 + lane];
        uint2 hC = reinterpret_cast<const uint2*>(g_Hh)[sC * 32 + lane];
        uint2 hD = reinterpret_cast<const uint2*>(g_Hh)[sD * 32 + lane];
        aA *= rh; aB *= rh; aC *= rh; aD *= rh;
        {
            float2 f01 = __half22float2(*reinterpret_cast<__half2*>(&hA.x));
            float2 f23 = __half22float2(*reinterpret_cast<__half2*>(&hA.y));
            acc.x += aA * f01.x; acc.y += aA * f01.y;
            acc.z += aA * f23.x; acc.w += aA * f23.y;
        }
        {
            float2 f01 = __half22float2(*reinterpret_cast<__half2*>(&hB.x));
            float2 f23 = __half22float2(*reinterpret_cast<__half2*>(&hB.y));
            acc.x += aB * f01.x; acc.y += aB * f01.y;
            acc.z += aB * f23.x; acc.w += aB * f23.y;
        }
        {
            float2 f01 = __half22float2(*reinterpret_cast<__half2*>(&hC.x));
            float2 f23 = __half22float2(*reinterpret_cast<__half2*>(&hC.y));
            acc.x += aC * f01.x; acc.y += aC * f01.y;
            acc.z += aC * f23.x; acc.w += aC * f23.y;
        }
        {
            float2 f01 = __half22float2(*reinterpret_cast<__half2*>(&hD.x));
            float2 f23 = __half22float2(*reinterpret_cast<__half2*>(&hD.y));
            acc.x += aD * f01.x; acc.y += aD * f01.y;
            acc.z += aD * f23.x; acc.w += aD * f23.y;
        }
    }
    for (; i < end; i++) {
        int s = g_csr_src[i];
        float a = g_ex[i * 4 + exh] * rh;
        uint2 hv = reinterpret_cast<const uint2*>(g_Hh)[s * 32 + lane];
        float2 f01 = __half22float2(*reinterpret_cast<__half2*>(&hv.x));
        float2 f23 = __half22float2(*reinterpret_cast<__half2*>(&hv.y));
        acc.x += a * f01.x;
        acc.y += a * f01.y;
        acc.z += a * f23.x;
        acc.w += a * f23.y;
    }
    float4 bb = reinterpret_cast<const float4*>(b)[lane];
    float4 o;
    o.x = fmaxf(acc.x + bb.x, 0.f);
    o.y = fmaxf(acc.y + bb.y, 0.f);
    o.z = fmaxf(acc.z + bb.z, 0.f);
    o.w = fmaxf(acc.w + bb.w, 0.f);
    reinterpret_cast<float4*>(sel_buf(aggsel))[d * 32 + lane] = o;
}

// ---------------- mean pool per graph (batch is sorted int32) ----------------
__device__ __forceinline__ int lbound_i(const int* a, int n, int v) {
    int lo = 0, hi = n;
    while (lo < hi) {
        int mid = (lo + hi) >> 1;
        if (a[mid] < v) lo = mid + 1; else hi = mid;
    }
    return lo;
}

__global__ void pool_kernel(const int* __restrict__ batch, int sel) {
    __shared__ int se[2];
    __shared__ float s[128];
    int g = blockIdx.x;
    int t = threadIdx.x;
    if (t == 0) {
        se[0] = lbound_i(batch, NN, g);
        se[1] = lbound_i(batch, NN, g + 1);
    }
    __syncthreads();
    int start = se[0], end = se[1];
    const float* h = sel_buf(sel);
    int f = t & 127;
    float acc = 0.f;
    for (int n = start + (t >> 7); n < end; n += 2)
        acc += h[n * 128 + f];
    if (t < 128) s[t] = acc;
    __syncthreads();
    if (t >= 128) s[f] += acc;   // exactly one writer per f
    __syncthreads();
    if (t < 128)
        g_pooled[g * 128 + t] = s[t] / fmaxf((float)(end - start), 1.0f);
}

// ---------------- final FC: [64,128] @ [128,10] + b ----------------
__global__ void fc_kernel(const float* __restrict__ fcW,
                          const float* __restrict__ fcb,
                          float* __restrict__ out) {
    int t = threadIdx.x;
    if (t >= NGRAPH * OUTCH) return;
    int g = t / OUTCH, o = t % OUTCH;
    float acc = fcb[o];
#pragma unroll 8
    for (int k = 0; k < 128; k++)
        acc += g_pooled[g * 128 + k] * fcW[k * OUTCH + o];
    out[t] = acc;
}

// ---------------- driver ----------------
static void run_layer(const float* x_ext, int xsel, int aggsel,
                      const float* W, const float* a_s, const float* a_d,
                      const float* b) {
    gemm_mma<<<(NN + 127) / 128, 256, GSM_BYTES>>>(x_ext, xsel, W, a_s, a_d);
    fused_edge<<<(NN + 7) / 8, 256>>>(aggsel, b);
}

extern "C" void kernel_launch(void* const* d_in, const int* in_sizes, int n_in,
                              void* d_out, int out_size) {
    const float* x     = (const float*)d_in[0];
    const int*   ei    = (const int*)d_in[1];    // int32 (JAX x64 disabled)
    const int*   batch = (const int*)d_in[2];
    const float* W1  = (const float*)d_in[3];
    const float* a1s = (const float*)d_in[4];
    const float* a1d = (const float*)d_in[5];
    const float* b1  = (const float*)d_in[6];
    const float* W2  = (const float*)d_in[7];
    const float* a2s = (const float*)d_in[8];
    const float* a2d = (const float*)d_in[9];
    const float* b2  = (const float*)d_in[10];
    const float* W3  = (const float*)d_in[11];
    const float* a3s = (const float*)d_in[12];
    const float* a3d = (const float*)d_in[13];
    const float* b3  = (const float*)d_in[14];
    const float* fcW = (const float*)d_in[15];
    const float* fcb = (const float*)d_in[16];

    cudaFuncSetAttribute(gemm_mma, cudaFuncAttributeMaxDynamicSharedMemorySize,
                         GSM_BYTES);

    int E = in_sizes[1] / 2;
    int total = E + NN;
    const int* srcs = ei;
    const int* dsts = ei + E;

    // CSR build (graph static across layers)
    init_deg<<<(NN + 255) / 256, 256>>>();
    count_deg<<<(E + 255) / 256, 256>>>(dsts, E);
    scan_deg<<<1, 1024>>>();
    scatter_edges<<<(total + 255) / 256, 256>>>(srcs, dsts, E, total);

    // layer 1: x -> P,  layer 2: P -> Q,  layer 3: Q -> P
    run_layer(x,       0, 1, W1, a1s, a1d, b1);
    run_layer(nullptr, 1, 2, W2, a2s, a2d, b2);
    run_layer(nullptr, 2, 1, W3, a3s, a3d, b3);

    pool_kernel<<<NGRAPH, 256>>>(batch, 1);
    fc_kernel<<<1, NGRAPH * OUTCH>>>(fcW, fcb, (float*)d_out);
}

// round 12
// speedup vs baseline: 1.2776x; 1.2776x over previous
#include <cuda_runtime.h>
#include <cuda_bf16.h>
#include <cuda_fp16.h>
#include <cstdint>

// Problem constants (fixed by the dataset)
#define NN      50000
#define FDIM    128
#define HEADS   4
#define NGRAPH  64
#define OUTCH   10
#define NEG     0.2f
#define MAXE    800000
#define MAXTOT  (MAXE + NN)   // edges + self loops

// ---------------- device scratch (static, no allocation) ----------------
__device__ __align__(16) __half g_Hh[NN * FDIM];   // gemm output (pre-bias h), fp16
__device__ __align__(16) float  g_P[NN * FDIM];    // ping buffer
__device__ __align__(16) float  g_Q[NN * FDIM];    // pong buffer
__device__ __align__(16) float  g_asrc[NN * HEADS];
__device__ __align__(16) float  g_adst[NN * HEADS];
__device__ __align__(16) float  g_ex[MAXTOT * HEADS]; // exp(e) per edge per head
__device__ __align__(16) float  g_pooled[NGRAPH * FDIM];
// W split into fp16 hi/lo, transposed to [n][k] (per layer, pre-GEMM)
__device__ __align__(16) __half g_Wt_hi[FDIM * FDIM];
__device__ __align__(16) __half g_Wt_lo[FDIM * FDIM];
// CSR by destination (built once per launch; graph static across layers)
__device__ int g_deg[NN];
__device__ int g_off[NN + 1];
__device__ int g_cursor[NN];
__device__ int g_csr_src[MAXTOT];

__device__ __forceinline__ float lrelu(float e) { return e > 0.f ? e : NEG * e; }

__device__ __forceinline__ float* sel_buf(int sel) {
    return sel == 1 ? g_P : g_Q;
}
__device__ __forceinline__ const float* sel_x(const float* ext, int sel) {
    return sel == 0 ? ext : (sel == 1 ? g_P : g_Q);
}

// ================= CSR build (once per launch) =================
__global__ void init_deg() {
    int i = blockIdx.x * blockDim.x + threadIdx.x;
    if (i < NN) g_deg[i] = 1;          // self loop
}
__global__ void count_deg(const int* __restrict__ dsts, int E) {
    int i = blockIdx.x * blockDim.x + threadIdx.x;
    if (i < E) atomicAdd(&g_deg[dsts[i]], 1);
}
// one block, 1024 threads: chunked exclusive scan of g_deg -> g_off, g_cursor
__global__ void scan_deg() {
    __shared__ int part[1024];
    const int CH = (NN + 1023) / 1024;   // 49
    int t = threadIdx.x;
    int base = t * CH;
    int s = 0;
    for (int k = 0; k < CH; k++) {
        int idx = base + k;
        if (idx < NN) s += g_deg[idx];
    }
    part[t] = s;
    __syncthreads();
    for (int off = 1; off < 1024; off <<= 1) {
        int v = (t >= off) ? part[t - off] : 0;
        __syncthreads();
        part[t] += v;
        __syncthreads();
    }
    int run = part[t] - s;     // exclusive start of this chunk
    for (int k = 0; k < CH; k++) {
        int idx = base + k;
        if (idx < NN) {
            g_off[idx]    = run;
            g_cursor[idx] = run;
            run += g_deg[idx];
        }
    }
    if (t == 0) g_off[NN] = part[1023];
}
__global__ void scatter_edges(const int* __restrict__ srcs,
                              const int* __restrict__ dsts, int E, int total) {
    int i = blockIdx.x * blockDim.x + threadIdx.x;
    if (i >= total) return;
    int s, d;
    if (i < E) { s = srcs[i]; d = dsts[i]; }
    else       { s = d = i - E; }
    int pos = atomicAdd(&g_cursor[d], 1);
    g_csr_src[pos] = s;
}

// ========== W -> fp16 hi/lo, transposed [n][k] (per layer) ==========
__global__ void conv_w(const float* __restrict__ W) {
    int i = blockIdx.x * blockDim.x + threadIdx.x;
    if (i >= FDIM * FDIM) return;
    int k = i >> 7, n = i & 127;
    float v = W[i];                       // W[k][n]
    __half h = __float2half_rn(v);
    __half l = __float2half_rn(v - __half2float(h));
    g_Wt_hi[n * FDIM + k] = h;
    g_Wt_lo[n * FDIM + k] = l;
}

// ======= GEMM via mma.sync, A in fp16 (hi only), B fp16 hi/lo split =======
// H = X(N,128) @ W(128,128). 128-row tile per block, 256 threads.
// 3 smem buffers (104KB) -> 2 blocks/SM. Fused attn-scalar epilogue.
#define SA 136                    // smem row stride in halfs (conflict-free)
#define GSM_BYTES (3 * 128 * SA * 2)   // Ahi, Bhi, Blo = 104448 B

__device__ __forceinline__ void mma16816(float* c, uint32_t a0, uint32_t a1,
                                         uint32_t a2, uint32_t a3,
                                         uint32_t b0, uint32_t b1) {
    asm volatile(
        "mma.sync.aligned.m16n8k16.row.col.f32.f16.f16.f32 "
        "{%0,%1,%2,%3}, {%4,%5,%6,%7}, {%8,%9}, {%0,%1,%2,%3};"
        : "+f"(c[0]), "+f"(c[1]), "+f"(c[2]), "+f"(c[3])
        : "r"(a0), "r"(a1), "r"(a2), "r"(a3), "r"(b0), "r"(b1));
}

__global__ void __launch_bounds__(256) gemm_mma(const float* __restrict__ Xext,
                                                int xsel,
                                                const float* __restrict__ a_s,
                                                const float* __restrict__ a_d) {
    extern __shared__ __align__(16) __half smh[];
    __half* Ahi = smh;
    __half* Bhi = Ahi + 128 * SA;
    __half* Blo = Bhi + 128 * SA;
    __shared__ float as_s[128], ad_s[128];

    const float* X = sel_x(Xext, xsel);
    const int tid  = threadIdx.x;
    const int lane = tid & 31;
    const int wid  = tid >> 5;
    const int g    = lane >> 2;       // 0..7
    const int c    = lane & 3;        // 0..3
    const int row0 = blockIdx.x * 128;
    const int arow = wid * 16 + g;    // fragment row within tile

    if (tid < 128) { as_s[tid] = a_s[tid]; ad_s[tid] = a_d[tid]; }

    // ---- fill A tile (X fp32 -> fp16) ----
    for (int it = tid; it < 128 * 32; it += 256) {
        int r = it >> 5, j = it & 31;          // j: float4 col
        float4 v = make_float4(0.f, 0.f, 0.f, 0.f);
        if (row0 + r < NN)
            v = reinterpret_cast<const float4*>(X)[(row0 + r) * 32 + j];
        __half2 h01 = __floats2half2_rn(v.x, v.y);
        __half2 h23 = __floats2half2_rn(v.z, v.w);
        uint2 hv = make_uint2(*(uint32_t*)&h01, *(uint32_t*)&h23);
        *reinterpret_cast<uint2*>(&Ahi[r * SA + 4 * j]) = hv;
    }
    // ---- fill B tiles from preconverted g_Wt ([n][k] fp16) ----
    for (int it = tid; it < 128 * 16; it += 256) {
        int n = it >> 4, j = it & 15;          // j: 8-half chunk
        *reinterpret_cast<uint4*>(&Bhi[n * SA + 8 * j]) =
            reinterpret_cast<const uint4*>(g_Wt_hi)[n * 16 + j];
        *reinterpret_cast<uint4*>(&Blo[n * SA + 8 * j]) =
            reinterpret_cast<const uint4*>(g_Wt_lo)[n * 16 + j];
    }
    __syncthreads();

    // ---- mainloop ----
    float acc[16][4];
#pragma unroll
    for (int nt = 0; nt < 16; nt++)
#pragma unroll
        for (int q = 0; q < 4; q++) acc[nt][q] = 0.f;

#pragma unroll
    for (int ks = 0; ks < 8; ks++) {
        const int kb = ks * 16 + 2 * c;
        uint32_t ah0 = *(uint32_t*)&Ahi[arow * SA + kb];
        uint32_t ah1 = *(uint32_t*)&Ahi[(arow + 8) * SA + kb];
        uint32_t ah2 = *(uint32_t*)&Ahi[arow * SA + kb + 8];
        uint32_t ah3 = *(uint32_t*)&Ahi[(arow + 8) * SA + kb + 8];
#pragma unroll
        for (int nt = 0; nt < 16; nt++) {
            const int nrow = nt * 8 + g;
            uint32_t bh0 = *(uint32_t*)&Bhi[nrow * SA + kb];
            uint32_t bh1 = *(uint32_t*)&Bhi[nrow * SA + kb + 8];
            uint32_t bl0 = *(uint32_t*)&Blo[nrow * SA + kb];
            uint32_t bl1 = *(uint32_t*)&Blo[nrow * SA + kb + 8];
            mma16816(acc[nt], ah0, ah1, ah2, ah3, bh0, bh1);
            mma16816(acc[nt], ah0, ah1, ah2, ah3, bl0, bl1);
        }
    }

    // ---- epilogue: attn scalars from accumulators + fp16 H store ----
    float ps[2][4], pd[2][4];
#pragma unroll
    for (int r2 = 0; r2 < 2; r2++)
#pragma unroll
        for (int h = 0; h < 4; h++) { ps[r2][h] = 0.f; pd[r2][h] = 0.f; }

#pragma unroll
    for (int nt = 0; nt < 16; nt++) {
        const int head = nt >> 2;
        const int col = nt * 8 + 2 * c;
        float s0 = as_s[col], s1 = as_s[col + 1];
        float d0 = ad_s[col], d1 = ad_s[col + 1];
        ps[0][head] += acc[nt][0] * s0 + acc[nt][1] * s1;
        pd[0][head] += acc[nt][0] * d0 + acc[nt][1] * d1;
        ps[1][head] += acc[nt][2] * s0 + acc[nt][3] * s1;
        pd[1][head] += acc[nt][2] * d0 + acc[nt][3] * d1;
    }
#pragma unroll
    for (int off = 1; off <= 2; off <<= 1)
#pragma unroll
        for (int r2 = 0; r2 < 2; r2++)
#pragma unroll
            for (int h = 0; h < 4; h++) {
                ps[r2][h] += __shfl_xor_sync(0xffffffffu, ps[r2][h], off);
                pd[r2][h] += __shfl_xor_sync(0xffffffffu, pd[r2][h], off);
            }
    if (c == 0) {
        int rA = row0 + arow, rB = rA + 8;
        if (rA < NN) {
            reinterpret_cast<float4*>(g_asrc)[rA] =
                make_float4(ps[0][0], ps[0][1], ps[0][2], ps[0][3]);
            reinterpret_cast<float4*>(g_adst)[rA] =
                make_float4(pd[0][0], pd[0][1], pd[0][2], pd[0][3]);
        }
        if (rB < NN) {
            reinterpret_cast<float4*>(g_asrc)[rB] =
                make_float4(ps[1][0], ps[1][1], ps[1][2], ps[1][3]);
            reinterpret_cast<float4*>(g_adst)[rB] =
                make_float4(pd[1][0], pd[1][1], pd[1][2], pd[1][3]);
        }
    }

    {
        int rA = row0 + arow, rB = rA + 8;
#pragma unroll
        for (int nt = 0; nt < 16; nt++) {
            const int col = nt * 8 + 2 * c;
            if (rA < NN) {
                __half2 v = __floats2half2_rn(acc[nt][0], acc[nt][1]);
                *reinterpret_cast<uint32_t*>(&g_Hh[rA * 128 + col]) =
                    *reinterpret_cast<uint32_t*>(&v);
            }
            if (rB < NN) {
                __half2 v = __floats2half2_rn(acc[nt][2], acc[nt][3]);
                *reinterpret_cast<uint32_t*>(&g_Hh[rB * 128 + col]) =
                    *reinterpret_cast<uint32_t*>(&v);
            }
        }
    }
}

// ======= fused softmax + aggregate: one warp per destination node =======
// No max pass (softmax shift-invariant; exp clamped at 30). exp(e) cached in
// g_ex. Pass 2: HALF-WARP per edge (16 lanes x uint4 = 256B row) -> 2 edges
// per iteration, LDG.128 gathers; halves combined with shfl_xor(16) at end.
__global__ void __launch_bounds__(256) fused_edge(int aggsel,
                                                  const float* __restrict__ b) {
    int gw   = (blockIdx.x * blockDim.x + threadIdx.x) >> 5;
    int lane = threadIdx.x & 31;
    if (gw >= NN) return;
    const int d   = gw;
    const int beg = g_off[d];
    const int end = g_off[d + 1];   // >= beg+1 (self loop)

    float4 ad4 = reinterpret_cast<const float4*>(g_adst)[d];

    // pass 1: exp(e) per edge (cached) + per-head denominator
    float s0 = 0.f, s1 = 0.f, s2 = 0.f, s3 = 0.f;
    for (int i = beg + lane; i < end; i += 32) {
        int s = g_csr_src[i];
        float4 as = reinterpret_cast<const float4*>(g_asrc)[s];
        float x0 = __expf(fminf(lrelu(as.x + ad4.x), 30.f));
        float x1 = __expf(fminf(lrelu(as.y + ad4.y), 30.f));
        float x2 = __expf(fminf(lrelu(as.z + ad4.z), 30.f));
        float x3 = __expf(fminf(lrelu(as.w + ad4.w), 30.f));
        reinterpret_cast<float4*>(g_ex)[i] = make_float4(x0, x1, x2, x3);
        s0 += x0; s1 += x1; s2 += x2; s3 += x3;
    }
#pragma unroll
    for (int off = 16; off > 0; off >>= 1) {
        s0 += __shfl_xor_sync(0xffffffffu, s0, off);
        s1 += __shfl_xor_sync(0xffffffffu, s1, off);
        s2 += __shfl_xor_sync(0xffffffffu, s2, off);
        s3 += __shfl_xor_sync(0xffffffffu, s3, off);
    }

    __threadfence_block();   // make this warp's g_ex stores visible to all lanes
    __syncwarp();

    const int half = lane >> 4;   // 0: edge i, 1: edge i+1
    const int fl   = lane & 15;   // feature group [8*fl, 8*fl+8)
    const int hl   = fl >> 2;     // head of this feature group
    float sh = (hl & 2) ? ((hl & 1) ? s3 : s2) : ((hl & 1) ? s1 : s0);
    float rh = 1.f / (sh + 1e-16f);

    float a8[8];
#pragma unroll
    for (int j = 0; j < 8; j++) a8[j] = 0.f;

    int i = beg;
#pragma unroll 2
    for (; i + 1 < end; i += 2) {
        int idx = i + half;
        int s = g_csr_src[idx];
        float a = g_ex[idx * 4 + hl] * rh;
        uint4 hv = reinterpret_cast<const uint4*>(g_Hh)[s * 16 + fl];
        float2 f0 = __half22float2(*reinterpret_cast<__half2*>(&hv.x));
        float2 f1 = __half22float2(*reinterpret_cast<__half2*>(&hv.y));
        float2 f2 = __half22float2(*reinterpret_cast<__half2*>(&hv.z));
        float2 f3 = __half22float2(*reinterpret_cast<__half2*>(&hv.w));
        a8[0] += a * f0.x; a8[1] += a * f0.y;
        a8[2] += a * f1.x; a8[3] += a * f1.y;
        a8[4] += a * f2.x; a8[5] += a * f2.y;
        a8[6] += a * f3.x; a8[7] += a * f3.y;
    }
    if (i < end) {                  // leftover edge: only half 0 contributes
        int s = g_csr_src[i];
        float a = (half == 0) ? g_ex[i * 4 + hl] * rh : 0.f;
        uint4 hv = reinterpret_cast<const uint4*>(g_Hh)[s * 16 + fl];
        float2 f0 = __half22float2(*reinterpret_cast<__half2*>(&hv.x));
        float2 f1 = __half22float2(*reinterpret_cast<__half2*>(&hv.y));
        float2 f2 = __half22float2(*reinterpret_cast<__half2*>(&hv.z));
        float2 f3 = __half22float2(*reinterpret_cast<__half2*>(&hv.w));
        a8[0] += a * f0.x; a8[1] += a * f0.y;
        a8[2] += a * f1.x; a8[3] += a * f1.y;
        a8[4] += a * f2.x; a8[5] += a * f2.y;
        a8[6] += a * f3.x; a8[7] += a * f3.y;
    }
    // combine the two half-warps
#pragma unroll
    for (int j = 0; j < 8; j++)
        a8[j] += __shfl_xor_sync(0xffffffffu, a8[j], 16);

    if (half == 0) {
        const float4* b4 = reinterpret_cast<const float4*>(b);
        float4 b0 = b4[fl * 2], b1 = b4[fl * 2 + 1];
        float4 o0, o1;
        o0.x = fmaxf(a8[0] + b0.x, 0.f);
        o0.y = fmaxf(a8[1] + b0.y, 0.f);
        o0.z = fmaxf(a8[2] + b0.z, 0.f);
        o0.w = fmaxf(a8[3] + b0.w, 0.f);
        o1.x = fmaxf(a8[4] + b1.x, 0.f);
        o1.y = fmaxf(a8[5] + b1.y, 0.f);
        o1.z = fmaxf(a8[6] + b1.z, 0.f);
        o1.w = fmaxf(a8[7] + b1.w, 0.f);
        float4* outp =
            reinterpret_cast<float4*>(sel_buf(aggsel) + d * 128 + fl * 8);
        outp[0] = o0;
        outp[1] = o1;
    }
}

// ---------------- mean pool per graph (batch is sorted int32) ----------------
__device__ __forceinline__ int lbound_i(const int* a, int n, int v) {
    int lo = 0, hi = n;
    while (lo < hi) {
        int mid = (lo + hi) >> 1;
        if (a[mid] < v) lo = mid + 1; else hi = mid;
    }
    return lo;
}

__global__ void pool_kernel(const int* __restrict__ batch, int sel) {
    __shared__ int se[2];
    __shared__ float s[128];
    int g = blockIdx.x;
    int t = threadIdx.x;
    if (t == 0) {
        se[0] = lbound_i(batch, NN, g);
        se[1] = lbound_i(batch, NN, g + 1);
    }
    __syncthreads();
    int start = se[0], end = se[1];
    const float* h = sel_buf(sel);
    int f = t & 127;
    float acc = 0.f;
    for (int n = start + (t >> 7); n < end; n += 2)
        acc += h[n * 128 + f];
    if (t < 128) s[t] = acc;
    __syncthreads();
    if (t >= 128) s[f] += acc;   // exactly one writer per f
    __syncthreads();
    if (t < 128)
        g_pooled[g * 128 + t] = s[t] / fmaxf((float)(end - start), 1.0f);
}

// ---------------- final FC: [64,128] @ [128,10] + b ----------------
__global__ void fc_kernel(const float* __restrict__ fcW,
                          const float* __restrict__ fcb,
                          float* __restrict__ out) {
    int t = threadIdx.x;
    if (t >= NGRAPH * OUTCH) return;
    int g = t / OUTCH, o = t % OUTCH;
    float acc = fcb[o];
#pragma unroll 8
    for (int k = 0; k < 128; k++)
        acc += g_pooled[g * 128 + k] * fcW[k * OUTCH + o];
    out[t] = acc;
}

// ---------------- driver ----------------
static void run_layer(const float* x_ext, int xsel, int aggsel,
                      const float* W, const float* a_s, const float* a_d,
                      const float* b) {
    conv_w<<<(FDIM * FDIM + 255) / 256, 256>>>(W);
    gemm_mma<<<(NN + 127) / 128, 256, GSM_BYTES>>>(x_ext, xsel, a_s, a_d);
    fused_edge<<<(NN + 7) / 8, 256>>>(aggsel, b);
}

extern "C" void kernel_launch(void* const* d_in, const int* in_sizes, int n_in,
                              void* d_out, int out_size) {
    const float* x     = (const float*)d_in[0];
    const int*   ei    = (const int*)d_in[1];    // int32 (JAX x64 disabled)
    const int*   batch = (const int*)d_in[2];
    const float* W1  = (const float*)d_in[3];
    const float* a1s = (const float*)d_in[4];
    const float* a1d = (const float*)d_in[5];
    const float* b1  = (const float*)d_in[6];
    const float* W2  = (const float*)d_in[7];
    const float* a2s = (const float*)d_in[8];
    const float* a2d = (const float*)d_in[9];
    const float* b2  = (const float*)d_in[10];
    const float* W3  = (const float*)d_in[11];
    const float* a3s = (const float*)d_in[12];
    const float* a3d = (const float*)d_in[13];
    const float* b3  = (const float*)d_in[14];
    const float* fcW = (const float*)d_in[15];
    const float* fcb = (const float*)d_in[16];

    cudaFuncSetAttribute(gemm_mma, cudaFuncAttributeMaxDynamicSharedMemorySize,
                         GSM_BYTES);

    int E = in_sizes[1] / 2;
    int total = E + NN;
    const int* srcs = ei;
    const int* dsts = ei + E;

    // CSR build (graph static across layers)
    init_deg<<<(NN + 255) / 256, 256>>>();
    count_deg<<<(E + 255) / 256, 256>>>(dsts, E);
    scan_deg<<<1, 1024>>>();
    scatter_edges<<<(total + 255) / 256, 256>>>(srcs, dsts, E, total);

    // layer 1: x -> P,  layer 2: P -> Q,  layer 3: Q -> P
    run_layer(x,       0, 1, W1, a1s, a1d, b1);
    run_layer(nullptr, 1, 2, W2, a2s, a2d, b2);
    run_layer(nullptr, 2, 1, W3, a3s, a3d, b3);

    pool_kernel<<<NGRAPH, 256>>>(batch, 1);
    fc_kernel<<<1, NGRAPH * OUTCH>>>(fcW, fcb, (float*)d_out);
}